// round 17
// baseline (speedup 1.0000x reference)
#include <cuda_runtime.h>
#include <math.h>
#include <stdint.h>

#define B 32
#define TIN 512
#define TOUT 800
#define NMEL 80
#define ENC 512
#define ARNN 1024
#define DRNN 1024
#define PRE 256
#define ATT 128
#define LOCF 32
#define LOCK 31
#define NB 256
#define NT 256

static __device__ float g_pren[(size_t)TOUT * PRE * B];    // [t][j][b]
static __device__ float g_pmemT[(size_t)B * ATT * TIN];    // [b][a][t]
static __device__ float g_ah[2][ARNN * B];                 // [h][b]
static __device__ float g_ahbm[2][B * ARNN];               // [b][h]
static __device__ float g_ac[ARNN * B];
static __device__ float g_dh[2][DRNN * B];
static __device__ float g_dhbm[2][B * DRNN];
static __device__ float g_dc[DRNN * B];
static __device__ float g_aw[B * TIN];
static __device__ float g_awc[B * TIN];
static __device__ float g_ctx[2][ENC * B];                 // [par][d][b]
static __device__ float g_ctxbm[2][B * ENC];               // [par][b][d]
static __device__ float g_epart[2][B * TIN];               // [ahalf][b][t]

struct PadCnt { unsigned v; unsigned pad[31]; };
static __device__ PadCnt g_gcnt[16];
static __device__ __align__(128) unsigned g_root;
static __device__ __align__(128) volatile unsigned g_epoch;

__device__ __forceinline__ float sigf(float x) { return __fdividef(1.f, 1.f + __expf(-x)); }
__device__ __forceinline__ float tanha(float x) {
    float y; asm("tanh.approx.f32 %0, %1;" : "=f"(y) : "f"(x)); return y;
}
__device__ __forceinline__ float wsum(float v) {
#pragma unroll
    for (int o = 16; o > 0; o >>= 1) v += __shfl_xor_sync(0xffffffffu, v, o);
    return v;
}
__device__ __forceinline__ float wmax(float v) {
#pragma unroll
    for (int o = 16; o > 0; o >>= 1) v = fmaxf(v, __shfl_xor_sync(0xffffffffu, v, o));
    return v;
}

__device__ __forceinline__ void gbar() {
    __syncthreads();
    if (threadIdx.x == 0) {
        unsigned e = g_epoch;
        __threadfence();
        unsigned r = atomicAdd(&g_gcnt[blockIdx.x >> 4].v, 1);
        if ((r & 15u) == 15u) {
            unsigned rr = atomicAdd(&g_root, 1);
            if ((rr & 15u) == 15u) { __threadfence(); g_epoch = e + 1; }
        }
        while (g_epoch == e) __nanosleep(32);
        __threadfence();
    }
    __syncthreads();
}

struct SLstm {
    float xs[2][4][32][B];       // [buf][kslice][kk][b]  32KB
    float zsp[4][16][36];        // [kslice][rowlocal][b]; pitch 36 floats = 144B (16B-aligned)
};
struct SAtt {
    float ahs[ARNN];
    float pqs[64]; float vs[64];
    float cat0[158]; float cat1[158];
    float cwsT[62][LOCF];
    float lls[64 * LOCF];
    float lfs[128][LOCF + 1];
    float ep[NT];
};
struct SSoft { float sw[TIN]; float red[8]; float sd[DRNN + ENC]; };
union Smem { SLstm l; SAtt a; SSoft s; };

__global__ void zero_kernel() {
    int i = blockIdx.x * blockDim.x + threadIdx.x;
    if (i < ARNN * B) {
        g_ah[0][i] = 0.f; g_ah[1][i] = 0.f; g_ahbm[0][i] = 0.f; g_ahbm[1][i] = 0.f; g_ac[i] = 0.f;
        g_dh[0][i] = 0.f; g_dh[1][i] = 0.f; g_dhbm[0][i] = 0.f; g_dhbm[1][i] = 0.f; g_dc[i] = 0.f;
    }
    if (i < B * TIN) { g_aw[i] = 0.f; g_awc[i] = 0.f; }
    if (i < ENC * B) { g_ctx[0][i] = 0.f; g_ctx[1][i] = 0.f; g_ctxbm[0][i] = 0.f; g_ctxbm[1][i] = 0.f; }
    if (i < 16) g_gcnt[i].v = 0;
    if (i == 0) { g_root = 0; g_epoch = 0; }
}

__global__ __launch_bounds__(256)
void prenet_kernel(const float* __restrict__ dec, const float* __restrict__ w1,
                   const float* __restrict__ w2) {
    int t = blockIdx.x >> 5, b = blockIdx.x & 31, tid = threadIdx.x;
    __shared__ float xm[NMEL];
    __shared__ float x1[PRE];
    if (tid < NMEL)
        xm[tid] = (t == 0) ? 0.f : dec[(size_t)b * NMEL * TOUT + (size_t)tid * TOUT + (t - 1)];
    __syncthreads();
    {
        const float* w = w1 + tid * NMEL;
        float s = 0.f;
#pragma unroll
        for (int m = 0; m < NMEL; ++m) s += xm[m] * w[m];
        x1[tid] = fmaxf(s, 0.f);
    }
    __syncthreads();
    {
        const float* w = w2 + tid * PRE;
        float s = 0.f;
#pragma unroll 8
        for (int k = 0; k < PRE; ++k) s += x1[k] * w[k];
        g_pren[((size_t)t * PRE + tid) * B + b] = fmaxf(s, 0.f);
    }
}

__global__ __launch_bounds__(128)
void pmem_kernel(const float* __restrict__ memory, const float* __restrict__ memw) {
    int b = blockIdx.x, tb = blockIdx.y * 16, a = threadIdx.x;
    __shared__ __align__(16) float xs[64][16];
    __shared__ float ws[128 * 65];
    float acc[16];
#pragma unroll
    for (int i = 0; i < 16; ++i) acc[i] = 0.f;
    for (int e0 = 0; e0 < ENC; e0 += 64) {
        __syncthreads();
#pragma unroll
        for (int i2 = 0; i2 < 8; ++i2) {
            int idx = a + i2 * 128, ee = idx & 63, tt = idx >> 6;
            xs[ee][tt] = memory[(size_t)b * TIN * ENC + (size_t)(tb + tt) * ENC + e0 + ee];
        }
#pragma unroll
        for (int i2 = 0; i2 < 64; ++i2) {
            int idx = a + i2 * 128, ee = idx & 63, aa = idx >> 6;
            ws[aa * 65 + ee] = memw[aa * ENC + e0 + ee];
        }
        __syncthreads();
#pragma unroll 4
        for (int ee = 0; ee < 64; ++ee) {
            float w = ws[a * 65 + ee];
            const float4* xr = (const float4*)&xs[ee][0];
            float4 v0 = xr[0], v1 = xr[1], v2 = xr[2], v3 = xr[3];
            acc[0] += w * v0.x; acc[1] += w * v0.y; acc[2] += w * v0.z; acc[3] += w * v0.w;
            acc[4] += w * v1.x; acc[5] += w * v1.y; acc[6] += w * v1.z; acc[7] += w * v1.w;
            acc[8] += w * v2.x; acc[9] += w * v2.y; acc[10] += w * v2.z; acc[11] += w * v2.w;
            acc[12] += w * v3.x; acc[13] += w * v3.y; acc[14] += w * v3.z; acc[15] += w * v3.w;
        }
    }
    float* o = g_pmemT + (size_t)b * ATT * TIN + (size_t)a * TIN + tb;
#pragma unroll
    for (int i = 0; i < 16; ++i) o[i] = acc[i];
}

// ---- LSTM: 256 blocks x 4 h each; split-K=4; thread = 2 gate-rows x 4 batches ----
template <int WA, int WB>
__device__ void lstm_fused(const float* __restrict__ srcA, const float* __restrict__ srcB,
                           const float* __restrict__ hprev,
                           const float* __restrict__ wih, const float* __restrict__ whh,
                           const float* __restrict__ bih, const float* __restrict__ bhh,
                           float* __restrict__ cst, float* __restrict__ hout,
                           float* __restrict__ hbm, SLstm& s) {
    constexpr int KX = WA + WB;
    constexpr int KTOT = KX + 1024;
    constexpr int SLICE = KTOT / 4;
    constexpr int NR = SLICE / 32;
    const int tid = threadIdx.x;
    const int ks = tid >> 6;
    const int sub = tid & 63;
    const int rp = sub >> 3;        // rowpair: rows 2rp, 2rp+1
    const int bg = sub & 7;
    const int h0 = blockIdx.x * 4;
    const int rl0 = rp * 2;
    const int j0 = (rl0 & 3) * 1024 + h0 + (rl0 >> 2);  // rl0 even -> j1 = j0 + 1024
    const int kbase = ks * SLICE;
    const float* wihr0 = wih + (size_t)j0 * KX;
    const float* wihr1 = wih + (size_t)(j0 + 1024) * KX;
    const float* whhr0 = whh + (size_t)j0 * 1024;
    const float* whhr1 = whh + (size_t)(j0 + 1024) * 1024;
    float a0[4] = {0, 0, 0, 0}, a1[4] = {0, 0, 0, 0};
#pragma unroll
    for (int i = 0; i < 16; ++i) {
        int idx = tid + i * NT;
        int ksl = idx >> 10, kk = (idx >> 5) & 31, bb = idx & 31;
        int k = ksl * SLICE + kk;
        float v;
        if (k < WA) v = srcA[k * B + bb];
        else if (k < KX) v = srcB[(k - WA) * B + bb];
        else v = hprev[(k - KX) * B + bb];
        s.xs[0][ksl][kk][bb] = v;
    }
    __syncthreads();
    for (int c = 0; c < NR; ++c) {
        const int k0 = kbase + c * 32;
        const bool ih = (k0 < KX);
        const float* w0 = ih ? (wihr0 + k0) : (whhr0 + (k0 - KX));
        const float* w1 = ih ? (wihr1 + k0) : (whhr1 + (k0 - KX));
        float xr[16];
        if (c + 1 < NR) {
#pragma unroll
            for (int i = 0; i < 16; ++i) {
                int idx = tid + i * NT;
                int ksl = idx >> 10, kk = (idx >> 5) & 31, bb = idx & 31;
                int k = ksl * SLICE + (c + 1) * 32 + kk;
                float v;
                if (k < WA) v = srcA[k * B + bb];
                else if (k < KX) v = srcB[(k - WA) * B + bb];
                else v = hprev[(k - KX) * B + bb];
                xr[i] = v;
            }
        }
        const float (*xb)[B] = s.xs[c & 1][ks];
#pragma unroll
        for (int q = 0; q < 8; ++q) {
            float4 wa = __ldg((const float4*)w0 + q);
            float4 wb = __ldg((const float4*)w1 + q);
            float4 x0 = *(const float4*)&xb[q * 4 + 0][bg * 4];
            float4 x1 = *(const float4*)&xb[q * 4 + 1][bg * 4];
            float4 x2 = *(const float4*)&xb[q * 4 + 2][bg * 4];
            float4 x3 = *(const float4*)&xb[q * 4 + 3][bg * 4];
            a0[0] += wa.x * x0.x; a0[1] += wa.x * x0.y; a0[2] += wa.x * x0.z; a0[3] += wa.x * x0.w;
            a1[0] += wb.x * x0.x; a1[1] += wb.x * x0.y; a1[2] += wb.x * x0.z; a1[3] += wb.x * x0.w;
            a0[0] += wa.y * x1.x; a0[1] += wa.y * x1.y; a0[2] += wa.y * x1.z; a0[3] += wa.y * x1.w;
            a1[0] += wb.y * x1.x; a1[1] += wb.y * x1.y; a1[2] += wb.y * x1.z; a1[3] += wb.y * x1.w;
            a0[0] += wa.z * x2.x; a0[1] += wa.z * x2.y; a0[2] += wa.z * x2.z; a0[3] += wa.z * x2.w;
            a1[0] += wb.z * x2.x; a1[1] += wb.z * x2.y; a1[2] += wb.z * x2.z; a1[3] += wb.z * x2.w;
            a0[0] += wa.w * x3.x; a0[1] += wa.w * x3.y; a0[2] += wa.w * x3.z; a0[3] += wa.w * x3.w;
            a1[0] += wb.w * x3.x; a1[1] += wb.w * x3.y; a1[2] += wb.w * x3.z; a1[3] += wb.w * x3.w;
        }
        if (c + 1 < NR) {
#pragma unroll
            for (int i = 0; i < 16; ++i) {
                int idx = tid + i * NT;
                s.xs[(c + 1) & 1][idx >> 10][(idx >> 5) & 31][idx & 31] = xr[i];
            }
        }
        __syncthreads();
    }
    *(float4*)&s.zsp[ks][rl0][bg * 4] = make_float4(a0[0], a0[1], a0[2], a0[3]);
    *(float4*)&s.zsp[ks][rl0 + 1][bg * 4] = make_float4(a1[0], a1[1], a1[2], a1[3]);
    __syncthreads();
    if (tid < 128) {
        const int bb = tid & 31, hl = tid >> 5;
        const int h = h0 + hl;
        float z[4];
#pragma unroll
        for (int gg = 0; gg < 4; ++gg) {
            const int j = gg * 1024 + h;
            float sv = bih[j] + bhh[j];
#pragma unroll
            for (int q = 0; q < 4; ++q) sv += s.zsp[q][hl * 4 + gg][bb];
            z[gg] = sv;
        }
        float c = cst[h * B + bb];
        float cn = sigf(z[1]) * c + sigf(z[0]) * tanhf(z[2]);
        cst[h * B + bb] = cn;
        float hv = sigf(z[3]) * tanhf(cn);
        hout[h * B + bb] = hv;
        hbm[bb * 1024 + h] = hv;
    }
    __syncthreads();
}

// ---- energy: 256 blocks = (b, q, ahalf); 128 t x 64 a each; partials to g_epart ----
__device__ void energy_phase(const float* __restrict__ qw, const float* __restrict__ convw,
                             const float* __restrict__ loclin, const float* __restrict__ vw,
                             int cur, SAtt& s) {
    const int b = blockIdx.x >> 3;
    const int q = (blockIdx.x >> 1) & 3;
    const int ah = blockIdx.x & 1;
    const int tbase = q * 128;
    const int a0 = ah * 64;
    const int tid = threadIdx.x, warp = tid >> 5, lane = tid & 31;
    ((float4*)s.ahs)[tid] = ((const float4*)&g_ahbm[cur][b * ARNN])[tid];
    for (int i = tid; i < 158; i += NT) {
        int tp = tbase - 15 + i;
        bool ok = (tp >= 0 && tp < TIN);
        s.cat0[i] = ok ? g_aw[b * TIN + tp] : 0.f;
        s.cat1[i] = ok ? g_awc[b * TIN + tp] : 0.f;
    }
    for (int i = tid; i < 62 * LOCF; i += NT) s.cwsT[i >> 5][i & 31] = convw[(i & 31) * 62 + (i >> 5)];
    for (int i = tid; i < 64 * LOCF; i += NT) s.lls[i] = loclin[a0 * LOCF + i];
    if (tid < 64) s.vs[tid] = vw[a0 + tid];
    __syncthreads();
    // pq for rows a0..a0+63: 8 warps x 8 rows
#pragma unroll 1
    for (int r = 0; r < 8; ++r) {
        int a = a0 + warp * 8 + r;
        const float4* w = (const float4*)(qw + (size_t)a * ARNN);
        const float4* hv = (const float4*)s.ahs;
        float acc = 0.f;
#pragma unroll
        for (int i = 0; i < 8; ++i) {
            float4 wq = __ldg(&w[lane + i * 32]);
            float4 xq = hv[lane + i * 32];
            acc += wq.x * xq.x + wq.y * xq.y + wq.z * xq.z + wq.w * xq.w;
        }
        acc = wsum(acc);
        if (lane == 0) s.pqs[warp * 8 + r] = acc;
    }
    // conv: thread (t = tid&127, fh = tid>>7) computes 16 filters
    {
        const int t = tid & 127, fh = tid >> 7;
        float lf[16];
#pragma unroll
        for (int i = 0; i < 16; ++i) lf[i] = 0.f;
#pragma unroll 2
        for (int kc = 0; kc < 62; ++kc) {
            float cv = (kc < 31) ? s.cat0[t + kc] : s.cat1[t + kc - 31];
            const float4* w = (const float4*)&s.cwsT[kc][fh * 16];
            float4 w0 = w[0], w1 = w[1], w2 = w[2], w3 = w[3];
            lf[0] += cv * w0.x; lf[1] += cv * w0.y; lf[2] += cv * w0.z; lf[3] += cv * w0.w;
            lf[4] += cv * w1.x; lf[5] += cv * w1.y; lf[6] += cv * w1.z; lf[7] += cv * w1.w;
            lf[8] += cv * w2.x; lf[9] += cv * w2.y; lf[10] += cv * w2.z; lf[11] += cv * w2.w;
            lf[12] += cv * w3.x; lf[13] += cv * w3.y; lf[14] += cv * w3.z; lf[15] += cv * w3.w;
        }
#pragma unroll
        for (int i = 0; i < 16; ++i) s.lfs[t][fh * 16 + i] = lf[i];
    }
    __syncthreads();
    // energies: thread (t, sh = tid>>7) handles 32 a-dims of this block's 64
    {
        const int t = tid & 127, sh = tid >> 7;
        float lfr[32];
#pragma unroll
        for (int i = 0; i < 32; ++i) lfr[i] = s.lfs[t][i];
        const float* pm = g_pmemT + (size_t)b * ATT * TIN + (size_t)a0 * TIN + tbase + t;
        float e = 0.f;
#pragma unroll 2
        for (int al = sh * 32; al < sh * 32 + 32; ++al) {
            float s0 = s.pqs[al] + __ldg(&pm[(size_t)al * TIN]);
            const float4* ll = (const float4*)&s.lls[al * LOCF];
#pragma unroll
            for (int i = 0; i < 8; ++i) {
                float4 lv = ll[i];
                s0 += lv.x * lfr[i * 4] + lv.y * lfr[i * 4 + 1] + lv.z * lfr[i * 4 + 2] + lv.w * lfr[i * 4 + 3];
            }
            e += s.vs[al] * tanha(s0);
        }
        s.ep[tid] = e;
    }
    __syncthreads();
    if (tid < 128)
        g_epart[ah][b * TIN + tbase + tid] = s.ep[tid] + s.ep[tid + 128];
}

// ---- softctx: 256 blocks = (b, d-oct); softmax over 512, ctx 64 d ----
__device__ void softctx_phase(const float* __restrict__ memory, const int* __restrict__ lens,
                              int t, int cur, float* __restrict__ out_align, SSoft& s) {
    const int b = blockIdx.x >> 3;
    const int o = blockIdx.x & 7;
    const int tid = threadIdx.x, warp = tid >> 5, lane = tid & 31;
    const int len = lens[b];
    float e0 = g_epart[0][b * TIN + tid] + g_epart[1][b * TIN + tid];
    float e1 = g_epart[0][b * TIN + tid + 256] + g_epart[1][b * TIN + tid + 256];
    if (tid >= len) e0 = -1e9f;
    if (tid + 256 >= len) e1 = -1e9f;
    float m = fmaxf(e0, e1);
    m = wmax(m);
    if (lane == 0) s.red[warp] = m;
    __syncthreads();
    {
        float mm = s.red[lane & 7];
#pragma unroll
        for (int oo = 4; oo > 0; oo >>= 1) mm = fmaxf(mm, __shfl_xor_sync(0xffffffffu, mm, oo));
        m = mm;
    }
    float p0 = __expf(e0 - m), p1 = __expf(e1 - m);
    float ps = wsum(p0 + p1);
    __syncthreads();
    if (lane == 0) s.red[warp] = ps;
    __syncthreads();
    {
        float ss = s.red[lane & 7];
#pragma unroll
        for (int oo = 4; oo > 0; oo >>= 1) ss += __shfl_xor_sync(0xffffffffu, ss, oo);
        ps = ss;
    }
    float inv = __fdividef(1.f, ps);
    float a0 = p0 * inv, a1 = p1 * inv;
    s.sw[tid] = a0; s.sw[tid + 256] = a1;
    if (o == 0) {
        g_aw[b * TIN + tid] = a0; g_aw[b * TIN + tid + 256] = a1;
        g_awc[b * TIN + tid] += a0; g_awc[b * TIN + tid + 256] += a1;
        float* oa = out_align + ((size_t)b * TOUT + t) * TIN;
        oa[tid] = a0; oa[tid + 256] = a1;
    }
    __syncthreads();
    // ctx for d = o*64 + dl; partial over t-quarter tq
    const int dl = tid & 63, tq = tid >> 6;
    const int d = o * 64 + dl;
    const float* mb = memory + (size_t)b * TIN * ENC + (size_t)(tq * 128) * ENC + d;
    float acc = 0.f;
#pragma unroll 4
    for (int tt = 0; tt < 128; ++tt)
        acc += s.sw[tq * 128 + tt] * __ldg(&mb[(size_t)tt * ENC]);
    s.sd[tq * 64 + dl] = acc;
    __syncthreads();
    if (tid < 64) {
        float c = s.sd[tid] + s.sd[64 + tid] + s.sd[128 + tid] + s.sd[192 + tid];
        g_ctx[cur][(o * 64 + tid) * B + b] = c;
        g_ctxbm[cur][b * ENC + o * 64 + tid] = c;
    }
    __syncthreads();
}

__device__ void proj_phase(const float* __restrict__ pw, const float* __restrict__ pb,
                           const float* __restrict__ gw, const float* __restrict__ gb,
                           int tp, int b, float* __restrict__ out_mel,
                           float* __restrict__ out_gate, SSoft& s) {
    const int par = tp & 1;
    const int tid = threadIdx.x, warp = tid >> 5, lane = tid & 31;
    __syncthreads();
    for (int i = tid; i < DRNN; i += NT) s.sd[i] = g_dhbm[par][b * DRNN + i];
    for (int i = tid; i < ENC; i += NT) s.sd[DRNN + i] = g_ctxbm[par][b * ENC + i];
    __syncthreads();
    for (int r = warp; r < NMEL + 1; r += 8) {
        const float4* w = (const float4*)((r < NMEL) ? (pw + (size_t)r * (DRNN + ENC)) : gw);
        const float4* x = (const float4*)s.sd;
        float acc = 0.f;
#pragma unroll
        for (int i = 0; i < 12; ++i) {
            float4 wq = __ldg(&w[lane + i * 32]);
            float4 xq = x[lane + i * 32];
            acc += wq.x * xq.x + wq.y * xq.y + wq.z * xq.z + wq.w * xq.w;
        }
        acc = wsum(acc);
        if (lane == 0) {
            if (r < NMEL) out_mel[(size_t)b * NMEL * TOUT + (size_t)r * TOUT + tp] = acc + pb[r];
            else out_gate[(size_t)b * TOUT + tp] = acc + gb[0];
        }
    }
}

__global__ __launch_bounds__(NT, 2)
void persist_kernel(const float* __restrict__ memory,
                    const float* __restrict__ awih, const float* __restrict__ awhh,
                    const float* __restrict__ abih, const float* __restrict__ abhh,
                    const float* __restrict__ qw, const float* __restrict__ vw,
                    const float* __restrict__ convw, const float* __restrict__ loclin,
                    const float* __restrict__ dwih, const float* __restrict__ dwhh,
                    const float* __restrict__ dbih, const float* __restrict__ dbhh,
                    const float* __restrict__ pw, const float* __restrict__ pb,
                    const float* __restrict__ gw, const float* __restrict__ gb,
                    const int* __restrict__ lens,
                    float* __restrict__ out_mel, float* __restrict__ out_gate,
                    float* __restrict__ out_align) {
    extern __shared__ __align__(16) char smraw[];
    Smem& sm = *reinterpret_cast<Smem*>(smraw);
    for (int t = 0; t < TOUT; ++t) {
        const int cur = t & 1, prev = cur ^ 1;
        lstm_fused<PRE, ENC>(g_pren + (size_t)t * PRE * B, &g_ctx[prev][0], &g_ah[prev][0],
                             awih, awhh, abih, abhh, g_ac, &g_ah[cur][0], &g_ahbm[cur][0], sm.l);
        gbar();
        energy_phase(qw, convw, loclin, vw, cur, sm.a);
        gbar();
        softctx_phase(memory, lens, t, cur, out_align, sm.s);
        if ((blockIdx.x & 7) == 7 && t > 0)
            proj_phase(pw, pb, gw, gb, t - 1, blockIdx.x >> 3, out_mel, out_gate, sm.s);
        gbar();
        lstm_fused<ARNN, ENC>(&g_ah[cur][0], &g_ctx[cur][0], &g_dh[prev][0],
                              dwih, dwhh, dbih, dbhh, g_dc, &g_dh[cur][0], &g_dhbm[cur][0], sm.l);
        gbar();
    }
    if ((blockIdx.x & 7) == 7)
        proj_phase(pw, pb, gw, gb, TOUT - 1, blockIdx.x >> 3, out_mel, out_gate, sm.s);
}

extern "C" void kernel_launch(void* const* d_in, const int* in_sizes, int n_in,
                              void* d_out, int out_size) {
    const float* memory = (const float*)d_in[0];
    const float* dec    = (const float*)d_in[1];
    const float* w1     = (const float*)d_in[2];
    const float* w2     = (const float*)d_in[3];
    const float* awih   = (const float*)d_in[4];
    const float* awhh   = (const float*)d_in[5];
    const float* abih   = (const float*)d_in[6];
    const float* abhh   = (const float*)d_in[7];
    const float* qw     = (const float*)d_in[8];
    const float* memw   = (const float*)d_in[9];
    const float* vw     = (const float*)d_in[10];
    const float* convw  = (const float*)d_in[11];
    const float* loclin = (const float*)d_in[12];
    const float* dwih   = (const float*)d_in[13];
    const float* dwhh   = (const float*)d_in[14];
    const float* dbih   = (const float*)d_in[15];
    const float* dbhh   = (const float*)d_in[16];
    const float* pw     = (const float*)d_in[17];
    const float* pb     = (const float*)d_in[18];
    const float* gw     = (const float*)d_in[19];
    const float* gb     = (const float*)d_in[20];
    const int*   lens   = (const int*)d_in[21];

    float* out_mel = (float*)d_out;
    float* out_gate = out_mel + (size_t)B * NMEL * TOUT;
    float* out_align = out_gate + (size_t)B * TOUT;

    cudaFuncSetAttribute(persist_kernel, cudaFuncAttributeMaxDynamicSharedMemorySize,
                         (int)sizeof(Smem));

    zero_kernel<<<(ARNN * B + 255) / 256, 256>>>();
    prenet_kernel<<<TOUT * B, 256>>>(dec, w1, w2);
    pmem_kernel<<<dim3(B, TIN / 16), 128>>>(memory, memw);
    persist_kernel<<<NB, NT, sizeof(Smem)>>>(memory, awih, awhh, abih, abhh, qw, vw,
                                             convw, loclin, dwih, dwhh, dbih, dbhh,
                                             pw, pb, gw, gb, lens,
                                             out_mel, out_gate, out_align);
}